// round 7
// baseline (speedup 1.0000x reference)
#include <cuda_runtime.h>
#include <cuda_bf16.h>
#include <cstdint>

#define N_NODES 8192
#define D 128
#define KNBR 8
#define LN_EPS 1e-5f

#define M_PLAIN 0
#define M_RELU  1
#define M_LN    2

#define MTILE 64
// SMEM layout (bytes): Ah[64x128 bf16]=16K, Al=16K, Wh[128x128 bf16]=32K, Wl=32K
#define OFF_AH 0
#define OFF_AL 16384
#define OFF_WH 32768
#define OFF_WL 65536
#define SMEM_TOTAL 98304
#define WTILE_BYTES 32768   // one pre-split W chunk [128 n][128 k] bf16

// ---------------- scratch (device globals: no allocation allowed) ----------
__device__ float g_buf0[N_NODES * D];
__device__ float g_buf1[N_NODES * D];
__device__ float g_buf2[N_NODES * D];
__device__ float g_dinv[N_NODES];
__device__ int   g_kcnt[N_NODES];
__device__ __align__(16) int   g_gn[N_NODES * KNBR];    // gcn kept list, pad=i
__device__ __align__(16) float g_gw[N_NODES * KNBR];    // dinv[j] or 0
__device__ __align__(16) int   g_pooln[N_NODES * KNBR]; // pool list, pad=first
__device__ float g_pmul[N_NODES];                       // 0 if leaf else 1
// pre-split, pre-swizzled weights: 10 chunks of [128 rows x 128 cols] bf16
__device__ __align__(16) unsigned char g_wh[10 * WTILE_BYTES];
__device__ __align__(16) unsigned char g_wl[10 * WTILE_BYTES];

// ---------------- helpers ---------------------------------------------------
__device__ __forceinline__ uint32_t smem_u32(const void* p) {
    uint32_t a;
    asm("{ .reg .u64 t; cvta.to.shared.u64 t, %1; cvt.u32.u64 %0, t; }"
        : "=r"(a) : "l"(p));
    return a;
}
__device__ __forceinline__ void ldsm4(uint32_t addr, uint32_t* r) {
    asm volatile("ldmatrix.sync.aligned.m8n8.x4.shared.b16 {%0,%1,%2,%3}, [%4];"
                 : "=r"(r[0]), "=r"(r[1]), "=r"(r[2]), "=r"(r[3]) : "r"(addr));
}
__device__ __forceinline__ void mma_bf16(float* d, const uint32_t* a,
                                         uint32_t b0, uint32_t b1) {
    asm volatile(
        "mma.sync.aligned.m16n8k16.row.col.f32.bf16.bf16.f32 "
        "{%0,%1,%2,%3}, {%4,%5,%6,%7}, {%8,%9}, {%0,%1,%2,%3};"
        : "+f"(d[0]), "+f"(d[1]), "+f"(d[2]), "+f"(d[3])
        : "r"(a[0]), "r"(a[1]), "r"(a[2]), "r"(a[3]), "r"(b0), "r"(b1));
}
static __device__ __forceinline__ uint32_t bf2u(__nv_bfloat162 v) {
    return *reinterpret_cast<uint32_t*>(&v);
}
// pack 8 consecutive floats -> hi uint4 / lo uint4 (bf16 pairs, low k = low bits)
__device__ __forceinline__ void split8(const float* f, uint4& hi, uint4& lo) {
    __nv_bfloat16 h[8];
    float l[8];
#pragma unroll
    for (int e = 0; e < 8; ++e) {
        h[e] = __float2bfloat16(f[e]);
        l[e] = f[e] - __bfloat162float(h[e]);
    }
    hi.x = bf2u(__halves2bfloat162(h[0], h[1]));
    hi.y = bf2u(__halves2bfloat162(h[2], h[3]));
    hi.z = bf2u(__halves2bfloat162(h[4], h[5]));
    hi.w = bf2u(__halves2bfloat162(h[6], h[7]));
    lo.x = bf2u(__floats2bfloat162_rn(l[0], l[1]));
    lo.y = bf2u(__floats2bfloat162_rn(l[2], l[3]));
    lo.z = bf2u(__floats2bfloat162_rn(l[4], l[5]));
    lo.w = bf2u(__floats2bfloat162_rn(l[6], l[7]));
}

// ---------------- graph prep: dedup + padded gather tables -----------------
__global__ void prep_kernel(const int* __restrict__ neigh,
                            const int* __restrict__ nbrc) {
    int i = blockIdx.x * blockDim.x + threadIdx.x;
    if (i >= N_NODES) return;
    int cnt = nbrc[i];
    cnt = cnt > KNBR ? KNBR : (cnt < 0 ? 0 : cnt);
    // pool table: original list padded with first entry (harmless for max)
    int first = cnt > 0 ? neigh[i * KNBR] : 0;
#pragma unroll
    for (int k = 0; k < KNBR; ++k)
        g_pooln[i * KNBR + k] = k < cnt ? neigh[i * KNBR + k] : first;
    g_pmul[i] = cnt > 0 ? 1.f : 0.f;
    // gcn: dedup, drop self
    int kept[KNBR];
    int kc = 0;
    for (int k = 0; k < cnt; ++k) {
        int nb = neigh[i * KNBR + k];
        if (nb == i) continue;
        bool dup = false;
        for (int t = 0; t < kc; ++t) if (kept[t] == nb) dup = true;
        if (!dup) kept[kc++] = nb;
    }
#pragma unroll
    for (int k = 0; k < KNBR; ++k)
        g_gn[i * KNBR + k] = k < kc ? kept[k] : i;   // pad = self (weight 0)
    g_kcnt[i] = kc;
    g_dinv[i] = rsqrtf((float)(kc + 1));
}

// ---------------- weight prep + gcn weight table ---------------------------
// blocks 0-9: split+swizzle W chunks; blocks 10-41: build g_gw
__global__ void prep_w_kernel(const float* __restrict__ gW,
                              const float* __restrict__ pW,
                              const float* __restrict__ mW) {
    int c = blockIdx.x, tid = threadIdx.x;
    if (c >= 10) {
        int i = (c - 10) * 256 + tid;        // node id
        int kc = g_kcnt[i];
#pragma unroll
        for (int k = 0; k < KNBR; ++k) {
            int j = g_gn[i * KNBR + k];
            g_gw[i * KNBR + k] = (k < kc) ? g_dinv[j] : 0.f;
        }
        return;
    }
    const float* src;
    int stride, coloff;
    if (c < 3)       { src = gW + c * 16384; stride = 128; coloff = 0; }
    else if (c == 3) { src = pW;             stride = 128; coloff = 0; }
    else { int l = (c - 4) >> 1, h = (c - 4) & 1;
           src = mW + l * 32768; stride = 256; coloff = h * 128; }
    unsigned char* wh = g_wh + c * WTILE_BYTES;
    unsigned char* wl = g_wl + c * WTILE_BYTES;
    for (int i = tid; i < 2048; i += 256) {       // 16B chunks
        int n = i >> 4, ch = i & 15;
        float f[8];
#pragma unroll
        for (int e = 0; e < 8; ++e) f[e] = src[n * stride + coloff + ch * 8 + e];
        uint4 hi, lo;
        split8(f, hi, lo);
        uint32_t off = (uint32_t)n * 256 + ((uint32_t)(ch ^ (n & 7)) << 4);
        *(uint4*)(wh + off) = hi;
        *(uint4*)(wl + off) = lo;
    }
}

// ---------------- HMMA GEMM: out = [A1 | pool(psrc)] @ W^T + b -------------
// hi/lo split: D = Ah@Wh + Ah@Wl + Al@Wh (fp32 accum in fragments)
__global__ __launch_bounds__(256, 2)
void mma_gemm_kernel(const float* __restrict__ A1, const float* __restrict__ psrc,
                     int wchunk,
                     const float* __restrict__ bias, const float* __restrict__ res,
                     const float* __restrict__ lng, const float* __restrict__ lnb,
                     float* __restrict__ out, int ostride, int ooff,
                     int mode, int nchunks) {
    extern __shared__ __align__(256) char smem_raw[];
    const uint32_t sbase = smem_u32(smem_raw);

    const int tid = threadIdx.x, wid = tid >> 5, lane = tid & 31;
    const int wm = wid & 1;          // row half: rows wm*32..+31
    const int wn = wid >> 1;         // col quarter: cols wn*32..+31
    const int m0 = blockIdx.x * MTILE;

    float acc[2][4][4];
#pragma unroll
    for (int i = 0; i < 2; ++i)
#pragma unroll
        for (int j = 0; j < 4; ++j)
#pragma unroll
            for (int r = 0; r < 4; ++r) acc[i][j][r] = 0.f;

    const int lrow = lane & 15, lhalf = lane >> 4;
    const int rowA0 = wm * 32 + lrow, rowA1 = rowA0 + 16;
    const int rowB0 = wn * 32 + lrow, rowB1 = rowB0 + 16;

    for (int c = 0; c < nchunks; ++c) {
        if (c) __syncthreads();
        if (c == 0) {
            // stage A1 rows
            for (int i = tid; i < 1024; i += 256) {
                int r = i >> 4, ch = i & 15;
                float f[8];
                float4 f0 = *(const float4*)&A1[(m0 + r) * D + ch * 8];
                float4 f1 = *(const float4*)&A1[(m0 + r) * D + ch * 8 + 4];
                f[0] = f0.x; f[1] = f0.y; f[2] = f0.z; f[3] = f0.w;
                f[4] = f1.x; f[5] = f1.y; f[6] = f1.z; f[7] = f1.w;
                uint4 hi, lo;
                split8(f, hi, lo);
                uint32_t off = (uint32_t)r * 256 + ((uint32_t)(ch ^ (r & 7)) << 4);
                *(uint4*)(smem_raw + OFF_AH + off) = hi;
                *(uint4*)(smem_raw + OFF_AL + off) = lo;
            }
        } else {
            // fused max-pool gather: A2[r] = pmul * max over 8 padded nbrs
            for (int i = tid; i < 1024; i += 256) {
                int r = i >> 4, ch = i & 15;
                int node = m0 + r;
                const int4* nl = (const int4*)(g_pooln + node * KNBR);
                int4 na = nl[0], nb = nl[1];
                float pm = g_pmul[node];
                const float* p = psrc + (size_t)ch * 8;
                float4 m0v, m1v;
                {
                    m0v = *(const float4*)&p[(size_t)na.x * D];
                    m1v = *(const float4*)&p[(size_t)na.x * D + 4];
                }
                int idx[7] = { na.y, na.z, na.w, nb.x, nb.y, nb.z, nb.w };
#pragma unroll
                for (int t = 0; t < 7; ++t) {
                    float4 r0 = *(const float4*)&p[(size_t)idx[t] * D];
                    float4 r1 = *(const float4*)&p[(size_t)idx[t] * D + 4];
                    m0v.x = fmaxf(m0v.x, r0.x); m0v.y = fmaxf(m0v.y, r0.y);
                    m0v.z = fmaxf(m0v.z, r0.z); m0v.w = fmaxf(m0v.w, r0.w);
                    m1v.x = fmaxf(m1v.x, r1.x); m1v.y = fmaxf(m1v.y, r1.y);
                    m1v.z = fmaxf(m1v.z, r1.z); m1v.w = fmaxf(m1v.w, r1.w);
                }
                float f[8];
                f[0] = pm * m0v.x; f[1] = pm * m0v.y;
                f[2] = pm * m0v.z; f[3] = pm * m0v.w;
                f[4] = pm * m1v.x; f[5] = pm * m1v.y;
                f[6] = pm * m1v.z; f[7] = pm * m1v.w;
                uint4 hi, lo;
                split8(f, hi, lo);
                uint32_t off = (uint32_t)r * 256 + ((uint32_t)(ch ^ (r & 7)) << 4);
                *(uint4*)(smem_raw + OFF_AH + off) = hi;
                *(uint4*)(smem_raw + OFF_AL + off) = lo;
            }
        }
        // stage W: pure copy of pre-swizzled chunk
        {
            const uint4* wh4 = (const uint4*)(g_wh + (wchunk + c) * WTILE_BYTES);
            const uint4* wl4 = (const uint4*)(g_wl + (wchunk + c) * WTILE_BYTES);
            uint4* dh = (uint4*)(smem_raw + OFF_WH);
            uint4* dl = (uint4*)(smem_raw + OFF_WL);
            for (int i = tid; i < 2048; i += 256) { dh[i] = wh4[i]; dl[i] = wl4[i]; }
        }
        __syncthreads();

#pragma unroll
        for (int pass = 0; pass < 3; ++pass) {
            const uint32_t aB = sbase + (pass < 2 ? OFF_AH : OFF_AL);
            const uint32_t wB = sbase + (pass == 1 ? OFF_WL : OFF_WH);
#pragma unroll
            for (int ks = 0; ks < 8; ++ks) {
                const int ch = ks * 2 + lhalf;
                uint32_t a0[4], a1[4], b0[4], b1[4];
                ldsm4(aB + rowA0 * 256 + ((ch ^ (rowA0 & 7)) << 4), a0);
                ldsm4(aB + rowA1 * 256 + ((ch ^ (rowA1 & 7)) << 4), a1);
                ldsm4(wB + rowB0 * 256 + ((ch ^ (rowB0 & 7)) << 4), b0);
                ldsm4(wB + rowB1 * 256 + ((ch ^ (rowB1 & 7)) << 4), b1);
                mma_bf16(acc[0][0], a0, b0[0], b0[2]);
                mma_bf16(acc[0][1], a0, b0[1], b0[3]);
                mma_bf16(acc[0][2], a0, b1[0], b1[2]);
                mma_bf16(acc[0][3], a0, b1[1], b1[3]);
                mma_bf16(acc[1][0], a1, b0[0], b0[2]);
                mma_bf16(acc[1][1], a1, b0[1], b0[3]);
                mma_bf16(acc[1][2], a1, b1[0], b1[2]);
                mma_bf16(acc[1][3], a1, b1[1], b1[3]);
            }
        }
    }

    // ---- epilogue ----------------------------------------------------------
    const int frow = lane >> 2, fcol = 2 * (lane & 3);

    if (mode != M_LN) {
#pragma unroll
        for (int i = 0; i < 2; ++i)
#pragma unroll
            for (int j = 0; j < 4; ++j) {
                int ncol = wn * 32 + j * 8 + fcol;
                float2 bj = *(const float2*)&bias[ncol];
                int m = m0 + wm * 32 + i * 16 + frow;
                float2 v0 = make_float2(acc[i][j][0] + bj.x, acc[i][j][1] + bj.y);
                float2 v1 = make_float2(acc[i][j][2] + bj.x, acc[i][j][3] + bj.y);
                if (mode == M_RELU) {
                    v0.x = fmaxf(v0.x, 0.f); v0.y = fmaxf(v0.y, 0.f);
                    v1.x = fmaxf(v1.x, 0.f); v1.y = fmaxf(v1.y, 0.f);
                }
                *(float2*)&out[m * ostride + ooff + ncol] = v0;
                *(float2*)&out[(m + 8) * ostride + ooff + ncol] = v1;
            }
        return;
    }

    // LN: relu(C+b) -> SMEM, then per-row LayerNorm with residual
    float* sC = (float*)smem_raw;             // [64][132]
    __syncthreads();
#pragma unroll
    for (int i = 0; i < 2; ++i)
#pragma unroll
        for (int j = 0; j < 4; ++j) {
            int ncol = wn * 32 + j * 8 + fcol;
            float2 bj = *(const float2*)&bias[ncol];
            int r = wm * 32 + i * 16 + frow;
            sC[r * 132 + ncol]       = fmaxf(acc[i][j][0] + bj.x, 0.f);
            sC[r * 132 + ncol + 1]   = fmaxf(acc[i][j][1] + bj.y, 0.f);
            sC[(r + 8) * 132 + ncol]     = fmaxf(acc[i][j][2] + bj.x, 0.f);
            sC[(r + 8) * 132 + ncol + 1] = fmaxf(acc[i][j][3] + bj.y, 0.f);
        }
    __syncthreads();

    {
        const int row = tid >> 2, q = tid & 3;     // 4 threads per row
        const int m = m0 + row;
        float v[32];
        float s = 0.f, ss = 0.f;
#pragma unroll
        for (int t = 0; t < 8; ++t) {
            int col = q * 32 + t * 4;
            float4 cv = *(float4*)&sC[row * 132 + col];
            float4 rv = *(const float4*)&res[m * D + col];
            v[4 * t + 0] = cv.x + rv.x; v[4 * t + 1] = cv.y + rv.y;
            v[4 * t + 2] = cv.z + rv.z; v[4 * t + 3] = cv.w + rv.w;
            s  += v[4 * t] + v[4 * t + 1] + v[4 * t + 2] + v[4 * t + 3];
            ss += v[4 * t] * v[4 * t] + v[4 * t + 1] * v[4 * t + 1] +
                  v[4 * t + 2] * v[4 * t + 2] + v[4 * t + 3] * v[4 * t + 3];
        }
#pragma unroll
        for (int off = 1; off < 4; off <<= 1) {
            s  += __shfl_xor_sync(0xffffffffu, s,  off);
            ss += __shfl_xor_sync(0xffffffffu, ss, off);
        }
        float mean = s * (1.0f / 128.0f);
        float rstd = rsqrtf(ss * (1.0f / 128.0f) - mean * mean + LN_EPS);
#pragma unroll
        for (int t = 0; t < 8; ++t) {
            int col = q * 32 + t * 4;
            float4 gj = *(const float4*)&lng[col];
            float4 oj = *(const float4*)&lnb[col];
            float4 o;
            o.x = (v[4 * t + 0] - mean) * rstd * gj.x + oj.x;
            o.y = (v[4 * t + 1] - mean) * rstd * gj.y + oj.y;
            o.z = (v[4 * t + 2] - mean) * rstd * gj.z + oj.z;
            o.w = (v[4 * t + 3] - mean) * rstd * gj.w + oj.w;
            *(float4*)&out[m * ostride + ooff + col] = o;
        }
    }
}

// ---------------- GCN: h = LN(relu(Ah @ nxt) + res)  (padded gather) -------
__global__ __launch_bounds__(256)
void prop_ln_kernel(const float* __restrict__ nxt, const float* __restrict__ res,
                    const float* __restrict__ lng, const float* __restrict__ lnb,
                    float* __restrict__ out, int ostride, int ooff) {
    const int lane = threadIdx.x & 31;
    const int i = (blockIdx.x << 3) + (threadIdx.x >> 5);
    const float di = g_dinv[i];

    const int4*   gn = (const int4*)(g_gn + i * KNBR);
    const float4* gw = (const float4*)(g_gw + i * KNBR);
    int4 n0 = gn[0], n1 = gn[1];
    float4 w0 = gw[0], w1 = gw[1];

    float4 t = ((const float4*)(nxt + i * D))[lane];
    float4 acc = make_float4(di * t.x, di * t.y, di * t.z, di * t.w);

    int   jj[8] = { n0.x, n0.y, n0.z, n0.w, n1.x, n1.y, n1.z, n1.w };
    float ww[8] = { w0.x, w0.y, w0.z, w0.w, w1.x, w1.y, w1.z, w1.w };
#pragma unroll
    for (int k = 0; k < 8; ++k) {
        float4 r = ((const float4*)(nxt + (size_t)jj[k] * D))[lane];
        acc.x += ww[k] * r.x; acc.y += ww[k] * r.y;
        acc.z += ww[k] * r.z; acc.w += ww[k] * r.w;
    }

    float4 rr = ((const float4*)(res + i * D))[lane];
    float4 v;
    v.x = fmaxf(di * acc.x, 0.f) + rr.x;
    v.y = fmaxf(di * acc.y, 0.f) + rr.y;
    v.z = fmaxf(di * acc.z, 0.f) + rr.z;
    v.w = fmaxf(di * acc.w, 0.f) + rr.w;
    float s  = v.x + v.y + v.z + v.w;
    float ss = v.x * v.x + v.y * v.y + v.z * v.z + v.w * v.w;
#pragma unroll
    for (int off = 16; off; off >>= 1) {
        s  += __shfl_xor_sync(0xffffffffu, s,  off);
        ss += __shfl_xor_sync(0xffffffffu, ss, off);
    }
    float mean = s * (1.0f / 128.0f);
    float rstd = rsqrtf(ss * (1.0f / 128.0f) - mean * mean + LN_EPS);
    float4 gj = ((const float4*)lng)[lane];
    float4 oj = ((const float4*)lnb)[lane];
    float4 o;
    o.x = (v.x - mean) * rstd * gj.x + oj.x;
    o.y = (v.y - mean) * rstd * gj.y + oj.y;
    o.z = (v.z - mean) * rstd * gj.z + oj.z;
    o.w = (v.w - mean) * rstd * gj.w + oj.w;
    *(float4*)&out[i * ostride + ooff + 4 * lane] = o;
}

// ---------------- driver ----------------------------------------------------
extern "C" void kernel_launch(void* const* d_in, const int* in_sizes, int n_in,
                              void* d_out, int out_size) {
    const float* x   = (const float*)d_in[0];
    const int*   nei = (const int*)  d_in[1];
    const int*   nbc = (const int*)  d_in[2];
    const float* gW  = (const float*)d_in[3];
    const float* gb  = (const float*)d_in[4];
    const float* glg = (const float*)d_in[5];
    const float* glb = (const float*)d_in[6];
    const float* pW  = (const float*)d_in[7];
    const float* pb  = (const float*)d_in[8];
    const float* mW  = (const float*)d_in[9];
    const float* mb  = (const float*)d_in[10];
    const float* slg = (const float*)d_in[11];
    const float* slb = (const float*)d_in[12];
    float* out = (float*)d_out;

    float *b0, *b1, *b2;
    cudaGetSymbolAddress((void**)&b0, g_buf0);
    cudaGetSymbolAddress((void**)&b1, g_buf1);
    cudaGetSymbolAddress((void**)&b2, g_buf2);

    cudaFuncSetAttribute(mma_gemm_kernel,
                         cudaFuncAttributeMaxDynamicSharedMemorySize, SMEM_TOTAL);

    const int GB = N_NODES / MTILE;    // 128 gemm tiles
    const int WB = N_NODES / 8;        // 1024 warp-per-node blocks

    prep_kernel<<<N_NODES / 256, 256>>>(nei, nbc);
    prep_w_kernel<<<10 + N_NODES / 256, 256>>>(gW, pW, mW);

    // ---- GCN branch ----
    mma_gemm_kernel<<<GB, 256, SMEM_TOTAL>>>(x, nullptr, 0, gb,
        nullptr, nullptr, nullptr, b0, D, 0, M_PLAIN, 1);
    prop_ln_kernel<<<WB, 256>>>(b0, b0, glg, glb, b1, D, 0);
    mma_gemm_kernel<<<GB, 256, SMEM_TOTAL>>>(b1, nullptr, 1, gb + D,
        nullptr, nullptr, nullptr, b0, D, 0, M_PLAIN, 1);
    prop_ln_kernel<<<WB, 256>>>(b0, b1, glg + D, glb + D, b1, D, 0);
    mma_gemm_kernel<<<GB, 256, SMEM_TOTAL>>>(b1, nullptr, 2, gb + 2 * D,
        nullptr, nullptr, nullptr, b0, D, 0, M_PLAIN, 1);
    prop_ln_kernel<<<WB, 256>>>(b0, b1, glg + 2 * D, glb + 2 * D, out, 2 * D, 0);

    // ---- SAGE branch (pool fused into merge GEMM staging) ----
    // ne1 = relu(x @ pW^T + pb) -> b0
    mma_gemm_kernel<<<GB, 256, SMEM_TOTAL>>>(x, nullptr, 3, pb,
        nullptr, nullptr, nullptr, b0, D, 0, M_RELU, 1);
    // s0 = relu([x | pool(b0)] @ mW0^T + mb0) -> b1
    mma_gemm_kernel<<<GB, 256, SMEM_TOTAL>>>(x, b0, 4, mb,
        nullptr, nullptr, nullptr, b1, D, 0, M_RELU, 2);
    // s1 = LN(relu([b1 | pool(b1)] @ mW1^T + mb1) + b1) -> b2
    mma_gemm_kernel<<<GB, 256, SMEM_TOTAL>>>(b1, b1, 6, mb + D,
        b1, slg, slb, b2, D, 0, M_LN, 2);
    // s2 = LN(relu([b2 | pool(b2)] @ mW2^T + mb2) + b2) -> out[:,128:]
    mma_gemm_kernel<<<GB, 256, SMEM_TOTAL>>>(b2, b2, 8, mb + 2 * D,
        b2, slg + D, slb + D, out, 2 * D, D, M_LN, 2);
}

// round 8
// speedup vs baseline: 1.0227x; 1.0227x over previous
#include <cuda_runtime.h>
#include <cuda_bf16.h>
#include <cstdint>

#define N_NODES 8192
#define D 128
#define KNBR 8
#define LN_EPS 1e-5f

#define M_PLAIN 0
#define M_RELU  1
#define M_LN    2

#define MTILE 64
// SMEM (bytes): Ah[64x128 bf16]=16K, Al=16K, Wh[128x128 bf16]=32K, Wl=32K
#define OFF_AH 0
#define OFF_AL 16384
#define OFF_WH 32768
#define OFF_WL 65536
#define SMEM_TOTAL 98304
#define WTILE_BYTES 32768   // one pre-split W chunk [128 n][128 k] bf16

// ---------------- scratch (device globals: no allocation allowed) ----------
__device__ float g_buf0[N_NODES * D];
__device__ float g_buf1[N_NODES * D];
__device__ float g_buf2[N_NODES * D];
__device__ float g_buf3[N_NODES * D];
__device__ float g_dinv[N_NODES];
__device__ int   g_kcnt[N_NODES];
__device__ __align__(16) int g_gn[N_NODES * KNBR];      // gcn kept list, pad=i
__device__ __align__(16) int g_pooln[N_NODES * KNBR];   // pool list, pad=first
__device__ float g_pmul[N_NODES];                       // 0 if leaf else 1
// pre-split, pre-swizzled weights: 10 chunks of [128 rows x 128 cols] bf16
__device__ __align__(16) unsigned char g_wh[10 * WTILE_BYTES];
__device__ __align__(16) unsigned char g_wl[10 * WTILE_BYTES];

// ---------------- job descriptors -------------------------------------------
struct GJob {
    const float* A1; const float* psrc;
    const float* bias; const float* res; const float* lng; const float* lnb;
    float* out;
    int wchunk, nchunks, mode, ostride, ooff;
};
struct PJob {
    const float* nxt; const float* res; const float* lng; const float* lnb;
    float* out;
    int ostride, ooff;
};

// ---------------- helpers ---------------------------------------------------
__device__ __forceinline__ uint32_t smem_u32(const void* p) {
    uint32_t a;
    asm("{ .reg .u64 t; cvta.to.shared.u64 t, %1; cvt.u32.u64 %0, t; }"
        : "=r"(a) : "l"(p));
    return a;
}
__device__ __forceinline__ void ldsm4(uint32_t addr, uint32_t* r) {
    asm volatile("ldmatrix.sync.aligned.m8n8.x4.shared.b16 {%0,%1,%2,%3}, [%4];"
                 : "=r"(r[0]), "=r"(r[1]), "=r"(r[2]), "=r"(r[3]) : "r"(addr));
}
__device__ __forceinline__ void mma_bf16(float* d, const uint32_t* a,
                                         uint32_t b0, uint32_t b1) {
    asm volatile(
        "mma.sync.aligned.m16n8k16.row.col.f32.bf16.bf16.f32 "
        "{%0,%1,%2,%3}, {%4,%5,%6,%7}, {%8,%9}, {%0,%1,%2,%3};"
        : "+f"(d[0]), "+f"(d[1]), "+f"(d[2]), "+f"(d[3])
        : "r"(a[0]), "r"(a[1]), "r"(a[2]), "r"(a[3]), "r"(b0), "r"(b1));
}
__device__ __forceinline__ void cp_async16(uint32_t saddr, const void* g) {
    asm volatile("cp.async.cg.shared.global [%0], [%1], 16;"
                 :: "r"(saddr), "l"(g));
}
#define CP_COMMIT() asm volatile("cp.async.commit_group;")
#define CP_WAIT0()  asm volatile("cp.async.wait_group 0;" ::: "memory")

static __device__ __forceinline__ uint32_t bf2u(__nv_bfloat162 v) {
    return *reinterpret_cast<uint32_t*>(&v);
}
// pack 8 consecutive floats -> hi uint4 / lo uint4 (bf16 pairs)
__device__ __forceinline__ void split8(const float* f, uint4& hi, uint4& lo) {
    __nv_bfloat16 h[8];
    float l[8];
#pragma unroll
    for (int e = 0; e < 8; ++e) {
        h[e] = __float2bfloat16(f[e]);
        l[e] = f[e] - __bfloat162float(h[e]);
    }
    hi.x = bf2u(__halves2bfloat162(h[0], h[1]));
    hi.y = bf2u(__halves2bfloat162(h[2], h[3]));
    hi.z = bf2u(__halves2bfloat162(h[4], h[5]));
    hi.w = bf2u(__halves2bfloat162(h[6], h[7]));
    lo.x = bf2u(__floats2bfloat162_rn(l[0], l[1]));
    lo.y = bf2u(__floats2bfloat162_rn(l[2], l[3]));
    lo.z = bf2u(__floats2bfloat162_rn(l[4], l[5]));
    lo.w = bf2u(__floats2bfloat162_rn(l[6], l[7]));
}

// ---------------- prep: blocks 0-9 split W, blocks 10-41 graph tables ------
__global__ void prep_all_kernel(const int* __restrict__ neigh,
                                const int* __restrict__ nbrc,
                                const float* __restrict__ gW,
                                const float* __restrict__ pW,
                                const float* __restrict__ mW) {
    int c = blockIdx.x, tid = threadIdx.x;
    if (c >= 10) {
        int i = (c - 10) * 256 + tid;
        int cnt = nbrc[i];
        cnt = cnt > KNBR ? KNBR : (cnt < 0 ? 0 : cnt);
        int first = cnt > 0 ? neigh[i * KNBR] : 0;
#pragma unroll
        for (int k = 0; k < KNBR; ++k)
            g_pooln[i * KNBR + k] = k < cnt ? neigh[i * KNBR + k] : first;
        g_pmul[i] = cnt > 0 ? 1.f : 0.f;
        int kept[KNBR];
        int kc = 0;
        for (int k = 0; k < cnt; ++k) {
            int nb = neigh[i * KNBR + k];
            if (nb == i) continue;
            bool dup = false;
            for (int t = 0; t < kc; ++t) if (kept[t] == nb) dup = true;
            if (!dup) kept[kc++] = nb;
        }
#pragma unroll
        for (int k = 0; k < KNBR; ++k)
            g_gn[i * KNBR + k] = k < kc ? kept[k] : i;
        g_kcnt[i] = kc;
        g_dinv[i] = rsqrtf((float)(kc + 1));
        return;
    }
    const float* src;
    int stride, coloff;
    if (c < 3)       { src = gW + c * 16384; stride = 128; coloff = 0; }
    else if (c == 3) { src = pW;             stride = 128; coloff = 0; }
    else { int l = (c - 4) >> 1, h = (c - 4) & 1;
           src = mW + l * 32768; stride = 256; coloff = h * 128; }
    unsigned char* wh = g_wh + c * WTILE_BYTES;
    unsigned char* wl = g_wl + c * WTILE_BYTES;
    for (int i = tid; i < 2048; i += 256) {       // 16B chunks
        int n = i >> 4, ch = i & 15;
        float f[8];
#pragma unroll
        for (int e = 0; e < 8; ++e) f[e] = src[n * stride + coloff + ch * 8 + e];
        uint4 hi, lo;
        split8(f, hi, lo);
        uint32_t off = (uint32_t)n * 256 + ((uint32_t)(ch ^ (n & 7)) << 4);
        *(uint4*)(wh + off) = hi;
        *(uint4*)(wl + off) = lo;
    }
}

// ---------------- GEMM body: out = [A1 | pool(psrc)] @ W^T + b -------------
// hi/lo split: D = Ah@Wh + Ah@Wl + Al@Wh (fp32 accum in fragments)
__device__ void gemm_body(const GJob& J, int bid, char* smem_raw) {
    const uint32_t sbase = smem_u32(smem_raw);
    const int tid = threadIdx.x, wid = tid >> 5, lane = tid & 31;
    const int wm = wid & 1, wn = wid >> 1;
    const int m0 = bid * MTILE;

    float acc[2][4][4];
#pragma unroll
    for (int i = 0; i < 2; ++i)
#pragma unroll
        for (int j = 0; j < 4; ++j)
#pragma unroll
            for (int r = 0; r < 4; ++r) acc[i][j][r] = 0.f;

    const int lrow = lane & 15, lhalf = lane >> 4;
    const int rowA0 = wm * 32 + lrow, rowA1 = rowA0 + 16;
    const int rowB0 = wn * 32 + lrow, rowB1 = rowB0 + 16;

    for (int c = 0; c < J.nchunks; ++c) {
        if (c) __syncthreads();
        // W: cp.async first so its latency hides behind A conversion
        {
            const unsigned char* wh = g_wh + (J.wchunk + c) * WTILE_BYTES;
            const unsigned char* wl = g_wl + (J.wchunk + c) * WTILE_BYTES;
#pragma unroll
            for (int i = 0; i < 8; ++i) {
                int t = tid + i * 256;
                cp_async16(sbase + OFF_WH + t * 16, wh + t * 16);
                cp_async16(sbase + OFF_WL + t * 16, wl + t * 16);
            }
            CP_COMMIT();
        }
        if (c == 0) {
            for (int i = tid; i < 1024; i += 256) {
                int r = i >> 4, ch = i & 15;
                float f[8];
                float4 f0 = *(const float4*)&J.A1[(m0 + r) * D + ch * 8];
                float4 f1 = *(const float4*)&J.A1[(m0 + r) * D + ch * 8 + 4];
                f[0] = f0.x; f[1] = f0.y; f[2] = f0.z; f[3] = f0.w;
                f[4] = f1.x; f[5] = f1.y; f[6] = f1.z; f[7] = f1.w;
                uint4 hi, lo;
                split8(f, hi, lo);
                uint32_t off = (uint32_t)r * 256 + ((uint32_t)(ch ^ (r & 7)) << 4);
                *(uint4*)(smem_raw + OFF_AH + off) = hi;
                *(uint4*)(smem_raw + OFF_AL + off) = lo;
            }
        } else {
            // fused max-pool gather: A2[r] = pmul * max over 8 padded nbrs
            for (int i = tid; i < 1024; i += 256) {
                int r = i >> 4, ch = i & 15;
                int node = m0 + r;
                const int4* nl = (const int4*)(g_pooln + node * KNBR);
                int4 na = nl[0], nb = nl[1];
                float pm = g_pmul[node];
                const float* p = J.psrc + (size_t)ch * 8;
                float4 m0v = *(const float4*)&p[(size_t)na.x * D];
                float4 m1v = *(const float4*)&p[(size_t)na.x * D + 4];
                int idx[7] = { na.y, na.z, na.w, nb.x, nb.y, nb.z, nb.w };
#pragma unroll
                for (int t = 0; t < 7; ++t) {
                    float4 r0 = *(const float4*)&p[(size_t)idx[t] * D];
                    float4 r1 = *(const float4*)&p[(size_t)idx[t] * D + 4];
                    m0v.x = fmaxf(m0v.x, r0.x); m0v.y = fmaxf(m0v.y, r0.y);
                    m0v.z = fmaxf(m0v.z, r0.z); m0v.w = fmaxf(m0v.w, r0.w);
                    m1v.x = fmaxf(m1v.x, r1.x); m1v.y = fmaxf(m1v.y, r1.y);
                    m1v.z = fmaxf(m1v.z, r1.z); m1v.w = fmaxf(m1v.w, r1.w);
                }
                float f[8];
                f[0] = pm * m0v.x; f[1] = pm * m0v.y;
                f[2] = pm * m0v.z; f[3] = pm * m0v.w;
                f[4] = pm * m1v.x; f[5] = pm * m1v.y;
                f[6] = pm * m1v.z; f[7] = pm * m1v.w;
                uint4 hi, lo;
                split8(f, hi, lo);
                uint32_t off = (uint32_t)r * 256 + ((uint32_t)(ch ^ (r & 7)) << 4);
                *(uint4*)(smem_raw + OFF_AH + off) = hi;
                *(uint4*)(smem_raw + OFF_AL + off) = lo;
            }
        }
        CP_WAIT0();
        __syncthreads();

#pragma unroll
        for (int pass = 0; pass < 3; ++pass) {
            const uint32_t aB = sbase + (pass < 2 ? OFF_AH : OFF_AL);
            const uint32_t wB = sbase + (pass == 1 ? OFF_WL : OFF_WH);
#pragma unroll
            for (int ks = 0; ks < 8; ++ks) {
                const int ch = ks * 2 + lhalf;
                uint32_t a0[4], a1[4], b0[4], b1[4];
                ldsm4(aB + rowA0 * 256 + ((ch ^ (rowA0 & 7)) << 4), a0);
                ldsm4(aB + rowA1 * 256 + ((ch ^ (rowA1 & 7)) << 4), a1);
                ldsm4(wB + rowB0 * 256 + ((ch ^ (rowB0 & 7)) << 4), b0);
                ldsm4(wB + rowB1 * 256 + ((ch ^ (rowB1 & 7)) << 4), b1);
                mma_bf16(acc[0][0], a0, b0[0], b0[2]);
                mma_bf16(acc[0][1], a0, b0[1], b0[3]);
                mma_bf16(acc[0][2], a0, b1[0], b1[2]);
                mma_bf16(acc[0][3], a0, b1[1], b1[3]);
                mma_bf16(acc[1][0], a1, b0[0], b0[2]);
                mma_bf16(acc[1][1], a1, b0[1], b0[3]);
                mma_bf16(acc[1][2], a1, b1[0], b1[2]);
                mma_bf16(acc[1][3], a1, b1[1], b1[3]);
            }
        }
    }

    const int frow = lane >> 2, fcol = 2 * (lane & 3);

    if (J.mode != M_LN) {
#pragma unroll
        for (int i = 0; i < 2; ++i)
#pragma unroll
            for (int j = 0; j < 4; ++j) {
                int ncol = wn * 32 + j * 8 + fcol;
                float2 bj = *(const float2*)&J.bias[ncol];
                int m = m0 + wm * 32 + i * 16 + frow;
                float2 v0 = make_float2(acc[i][j][0] + bj.x, acc[i][j][1] + bj.y);
                float2 v1 = make_float2(acc[i][j][2] + bj.x, acc[i][j][3] + bj.y);
                if (J.mode == M_RELU) {
                    v0.x = fmaxf(v0.x, 0.f); v0.y = fmaxf(v0.y, 0.f);
                    v1.x = fmaxf(v1.x, 0.f); v1.y = fmaxf(v1.y, 0.f);
                }
                *(float2*)&J.out[m * J.ostride + J.ooff + ncol] = v0;
                *(float2*)&J.out[(m + 8) * J.ostride + J.ooff + ncol] = v1;
            }
        return;
    }

    // LN: relu(C+b) -> SMEM, then per-row LayerNorm with residual
    float* sC = (float*)smem_raw;             // [64][132]
    __syncthreads();
#pragma unroll
    for (int i = 0; i < 2; ++i)
#pragma unroll
        for (int j = 0; j < 4; ++j) {
            int ncol = wn * 32 + j * 8 + fcol;
            float2 bj = *(const float2*)&J.bias[ncol];
            int r = wm * 32 + i * 16 + frow;
            sC[r * 132 + ncol]           = fmaxf(acc[i][j][0] + bj.x, 0.f);
            sC[r * 132 + ncol + 1]       = fmaxf(acc[i][j][1] + bj.y, 0.f);
            sC[(r + 8) * 132 + ncol]     = fmaxf(acc[i][j][2] + bj.x, 0.f);
            sC[(r + 8) * 132 + ncol + 1] = fmaxf(acc[i][j][3] + bj.y, 0.f);
        }
    __syncthreads();

    {
        const int row = tid >> 2, q = tid & 3;     // 4 threads per row
        const int m = m0 + row;
        float v[32];
        float s = 0.f, ss = 0.f;
#pragma unroll
        for (int t = 0; t < 8; ++t) {
            int col = q * 32 + t * 4;
            float4 cv = *(float4*)&sC[row * 132 + col];
            float4 rv = *(const float4*)&J.res[m * D + col];
            v[4 * t + 0] = cv.x + rv.x; v[4 * t + 1] = cv.y + rv.y;
            v[4 * t + 2] = cv.z + rv.z; v[4 * t + 3] = cv.w + rv.w;
            s  += v[4 * t] + v[4 * t + 1] + v[4 * t + 2] + v[4 * t + 3];
            ss += v[4 * t] * v[4 * t] + v[4 * t + 1] * v[4 * t + 1] +
                  v[4 * t + 2] * v[4 * t + 2] + v[4 * t + 3] * v[4 * t + 3];
        }
#pragma unroll
        for (int off = 1; off < 4; off <<= 1) {
            s  += __shfl_xor_sync(0xffffffffu, s,  off);
            ss += __shfl_xor_sync(0xffffffffu, ss, off);
        }
        float mean = s * (1.0f / 128.0f);
        float rstd = rsqrtf(ss * (1.0f / 128.0f) - mean * mean + LN_EPS);
#pragma unroll
        for (int t = 0; t < 8; ++t) {
            int col = q * 32 + t * 4;
            float4 gj = *(const float4*)&J.lng[col];
            float4 oj = *(const float4*)&J.lnb[col];
            float4 o;
            o.x = (v[4 * t + 0] - mean) * rstd * gj.x + oj.x;
            o.y = (v[4 * t + 1] - mean) * rstd * gj.y + oj.y;
            o.z = (v[4 * t + 2] - mean) * rstd * gj.z + oj.z;
            o.w = (v[4 * t + 3] - mean) * rstd * gj.w + oj.w;
            *(float4*)&J.out[m * J.ostride + J.ooff + col] = o;
        }
    }
}

// ---------------- prop body: 64 nodes per block, warp per node -------------
__device__ void prop_body(const PJob& P, int blk) {
    const int lane = threadIdx.x & 31, wid = threadIdx.x >> 5;
    const int base = blk * 64 + wid * 8;
    for (int t = 0; t < 8; ++t) {
        const int i = base + t;
        const float di = g_dinv[i];
        float4 s4 = ((const float4*)(P.nxt + (size_t)i * D))[lane];
        float4 acc = make_float4(di * s4.x, di * s4.y, di * s4.z, di * s4.w);
        const int kc = g_kcnt[i];
        const int* kn = g_gn + i * KNBR;
        for (int k = 0; k < kc; ++k) {
            int j = kn[k];
            float dj = g_dinv[j];
            float4 r = ((const float4*)(P.nxt + (size_t)j * D))[lane];
            acc.x += dj * r.x; acc.y += dj * r.y;
            acc.z += dj * r.z; acc.w += dj * r.w;
        }
        float4 rr = ((const float4*)(P.res + (size_t)i * D))[lane];
        float4 v;
        v.x = fmaxf(di * acc.x, 0.f) + rr.x;
        v.y = fmaxf(di * acc.y, 0.f) + rr.y;
        v.z = fmaxf(di * acc.z, 0.f) + rr.z;
        v.w = fmaxf(di * acc.w, 0.f) + rr.w;
        float s  = v.x + v.y + v.z + v.w;
        float ss = v.x * v.x + v.y * v.y + v.z * v.z + v.w * v.w;
#pragma unroll
        for (int off = 16; off; off >>= 1) {
            s  += __shfl_xor_sync(0xffffffffu, s,  off);
            ss += __shfl_xor_sync(0xffffffffu, ss, off);
        }
        float mean = s * (1.0f / 128.0f);
        float rstd = rsqrtf(ss * (1.0f / 128.0f) - mean * mean + LN_EPS);
        float4 gj = ((const float4*)P.lng)[lane];
        float4 oj = ((const float4*)P.lnb)[lane];
        float4 o;
        o.x = (v.x - mean) * rstd * gj.x + oj.x;
        o.y = (v.y - mean) * rstd * gj.y + oj.y;
        o.z = (v.z - mean) * rstd * gj.z + oj.z;
        o.w = (v.w - mean) * rstd * gj.w + oj.w;
        *(float4*)&P.out[(size_t)i * P.ostride + P.ooff + 4 * lane] = o;
    }
}

// ---------------- combo dispatcher ------------------------------------------
__global__ __launch_bounds__(256, 2)
void combo_kernel(GJob g0, int n0, GJob g1, int n1, PJob p) {
    extern __shared__ __align__(256) char smem_raw[];
    const int b = blockIdx.x;
    if (b < n0)            gemm_body(g0, b, smem_raw);
    else if (b < n0 + n1)  gemm_body(g1, b - n0, smem_raw);
    else                   prop_body(p, b - n0 - n1);
}

// ---------------- driver ----------------------------------------------------
extern "C" void kernel_launch(void* const* d_in, const int* in_sizes, int n_in,
                              void* d_out, int out_size) {
    const float* x   = (const float*)d_in[0];
    const int*   nei = (const int*)  d_in[1];
    const int*   nbc = (const int*)  d_in[2];
    const float* gW  = (const float*)d_in[3];
    const float* gb  = (const float*)d_in[4];
    const float* glg = (const float*)d_in[5];
    const float* glb = (const float*)d_in[6];
    const float* pW  = (const float*)d_in[7];
    const float* pb  = (const float*)d_in[8];
    const float* mW  = (const float*)d_in[9];
    const float* mb  = (const float*)d_in[10];
    const float* slg = (const float*)d_in[11];
    const float* slb = (const float*)d_in[12];
    float* out = (float*)d_out;

    float *b0, *b1, *b2, *b3;
    cudaGetSymbolAddress((void**)&b0, g_buf0);
    cudaGetSymbolAddress((void**)&b1, g_buf1);
    cudaGetSymbolAddress((void**)&b2, g_buf2);
    cudaGetSymbolAddress((void**)&b3, g_buf3);

    cudaFuncSetAttribute(combo_kernel,
                         cudaFuncAttributeMaxDynamicSharedMemorySize, SMEM_TOTAL);

    const int GB = N_NODES / MTILE;    // 128 gemm tiles
    const int PB = N_NODES / 64;       // 128 prop blocks

    GJob Z = {};                       // dummy
    PJob ZP = {};

    // G jobs
    GJob G0 = { x,  nullptr, gb,          nullptr, nullptr, nullptr, b0, 0, 1, M_PLAIN, D, 0 };
    GJob G1 = { b1, nullptr, gb + D,      nullptr, nullptr, nullptr, b0, 1, 1, M_PLAIN, D, 0 };
    GJob G2 = { b1, nullptr, gb + 2 * D,  nullptr, nullptr, nullptr, b0, 2, 1, M_PLAIN, D, 0 };
    // S jobs
    GJob S0 = { x,  nullptr, pb,          nullptr, nullptr, nullptr, b2, 3, 1, M_RELU, D, 0 };
    GJob S1 = { x,  b2,      mb,          nullptr, nullptr, nullptr, b3, 4, 2, M_RELU, D, 0 };
    GJob S2 = { b3, b3,      mb + D,      b3, slg, slb,               b2, 6, 2, M_LN,   D, 0 };
    GJob S3 = { b2, b2,      mb + 2 * D,  b2, slg + D, slb + D,       out, 8, 2, M_LN, 2 * D, D };
    // P jobs
    PJob P0 = { b0, b0, glg,         glb,         b1,  D,     0 };
    PJob P1 = { b0, b1, glg + D,     glb + D,     b1,  D,     0 };
    PJob P2 = { b0, b1, glg + 2 * D, glb + 2 * D, out, 2 * D, 0 };

    prep_all_kernel<<<10 + N_NODES / 256, 256>>>(nei, nbc, gW, pW, mW);

    // step1: G0 | S0
    combo_kernel<<<2 * GB, 256, SMEM_TOTAL>>>(G0, GB, S0, GB, ZP);
    // step2: S1 | P0
    combo_kernel<<<GB + PB, 256, SMEM_TOTAL>>>(S1, GB, Z, 0, P0);
    // step3: G1 | S2
    combo_kernel<<<2 * GB, 256, SMEM_TOTAL>>>(G1, GB, S2, GB, ZP);
    // step4: S3 | P1
    combo_kernel<<<GB + PB, 256, SMEM_TOTAL>>>(S3, GB, Z, 0, P1);
    // step5: G2
    combo_kernel<<<GB, 256, SMEM_TOTAL>>>(G2, GB, Z, 0, ZP);
    // step6: P2
    combo_kernel<<<PB, 256, SMEM_TOTAL>>>(Z, 0, Z, 0, P2);
}